// round 6
// baseline (speedup 1.0000x reference)
#include <cuda_runtime.h>
#include <cstdint>

#define NSP     2048
#define BATCH   64
#define NSTEP   1000
#define KEX     32            // steps between ghost exchanges
#define GW      64            // ghost width per side (= 2 * KEX)
#define OWNW    256           // owned elems per warp
#define COVER   384           // OWNW + 2*GW
#define EPT     12            // elems per thread (COVER/32)
#define THREADS 128           // 4 warps per CTA
#define OWN_CTA 1024          // owned per CTA (half row)
#define NBUF    6             // staging ring depth (frames)

typedef unsigned long long u64;

__device__ __forceinline__ u64 pk(float lo, float hi) {
    u64 r; asm("mov.b64 %0,{%1,%2};" : "=l"(r) : "f"(lo), "f"(hi)); return r;
}
__device__ __forceinline__ void upk(u64 v, float& lo, float& hi) {
    asm("mov.b64 {%0,%1},%2;" : "=f"(lo), "=f"(hi) : "l"(v));
}
__device__ __forceinline__ u64 fma2(u64 a, u64 b, u64 c) {
    u64 d; asm("fma.rn.f32x2 %0,%1,%2,%3;" : "=l"(d) : "l"(a), "l"(b), "l"(c)); return d;
}
__device__ __forceinline__ u64 add2(u64 a, u64 b) {
    u64 d; asm("add.rn.f32x2 %0,%1,%2;" : "=l"(d) : "l"(a), "l"(b)); return d;
}
__device__ __forceinline__ u64 mul2(u64 a, u64 b) {
    u64 d; asm("mul.rn.f32x2 %0,%1,%2;" : "=l"(d) : "l"(a), "l"(b)); return d;
}

__global__ void __cluster_dims__(2, 1, 1) __launch_bounds__(THREADS, 1)
ks_kernel(const float* __restrict__ u0,
          const float* __restrict__ cp,
          const float* __restrict__ ap,
          const float* __restrict__ bp,
          float* __restrict__ out) {
    __shared__ alignas(16) float sh_ex[OWN_CTA];            // exchange staging (4 KB)
    __shared__ alignas(16) float sh_st[4][NBUF][OWNW];      // store ring: 24 KB

    const int row  = blockIdx.x >> 1;
    const int half = blockIdx.x & 1;
    const int w    = threadIdx.x >> 5;
    const int lane = threadIdx.x & 31;

    const float dt = 0.01f;
    const float Af = -0.5f * dt * (*cp);
    const float Bc = -dt * (*ap);
    const float Cc = -dt * (*bp);
    const float c0f = 1.0f - 2.0f * Bc + 6.0f * Cc;
    const float c1f = Bc - 4.0f * Cc;
    const u64 C0 = pk(c0f, c0f), C1 = pk(c1f, c1f), C2 = pk(Cc, Cc);
    const u64 AV = pk(Af, Af),   M1 = pk(-1.0f, -1.0f);

    // warp cover: local coord j in [0, COVER); global row pos = base + j (mod NSP)
    const int base = half * OWN_CTA + w * OWNW - GW;    // may be negative
    const int j0   = lane * EPT;

    // ---- initial load: 3 float4 groups per thread, periodic wrap ----
    u64 P[6];
    const float* urow = u0 + (size_t)row * NSP;
    #pragma unroll
    for (int g = 0; g < 3; g++) {
        int pos = (base + j0 + 4 * g) & (NSP - 1);
        float4 v = *reinterpret_cast<const float4*>(urow + pos);
        P[2 * g]     = pk(v.x, v.y);
        P[2 * g + 1] = pk(v.z, v.w);
    }

    // ---- frame 0 = u0 (owned groups only; d_out is poisoned) ----
    {
        float* o0 = out + (size_t)row * NSP;
        #pragma unroll
        for (int g = 0; g < 3; g++) {
            int j = j0 + 4 * g;
            if (j >= GW && j < GW + OWNW) {
                ulonglong2 v; v.x = P[2 * g]; v.y = P[2 * g + 1];
                *reinterpret_cast<ulonglong2*>(o0 + base + j) = v;
            }
        }
    }

    const uint32_t shbase = (uint32_t)__cvta_generic_to_shared(sh_ex);
    const uint32_t st0    = (uint32_t)__cvta_generic_to_shared(&sh_st[w][0][0]);
    const uint32_t peer   = (uint32_t)(half ^ 1);

    // frame-1 pointer for this warp's owned slice (1 KB contiguous)
    const size_t FR = (size_t)BATCH * NSP;
    float* gbase = out + FR + (size_t)row * NSP + (half * OWN_CTA + w * OWNW);

    // initial cluster arrive — pairs with the first exchange's wait
    asm volatile("barrier.cluster.arrive.aligned;" ::: "memory");

    #pragma unroll 1
    for (int t = 0; t < NSTEP; t++) {
        if (t > 0 && (t & (KEX - 1)) == 0) {
            // ===== ghost exchange (every KEX steps) =====
            asm volatile("barrier.cluster.wait.aligned;" ::: "memory");

            // publish my owned 256 elems to sh_ex
            #pragma unroll
            for (int g = 0; g < 3; g++) {
                int j = j0 + 4 * g;
                if (j >= GW && j < GW + OWNW) {
                    float a, b, c, d;
                    upk(P[2 * g], a, b); upk(P[2 * g + 1], c, d);
                    *reinterpret_cast<float4*>(&sh_ex[w * OWNW + (j - GW)]) =
                        make_float4(a, b, c, d);
                }
            }
            __syncthreads();
            asm volatile("barrier.cluster.arrive.aligned;" ::: "memory");
            asm volatile("barrier.cluster.wait.aligned;"   ::: "memory"); // both ready

            // refill ghost groups from own sh_ex or peer sh_ex (DSMEM)
            #pragma unroll
            for (int g = 0; g < 3; g++) {
                int j = j0 + 4 * g;
                if (j < GW || j >= GW + OWNW) {
                    int pos = (base + j) & (NSP - 1);
                    int h2  = pos >> 10;            // owning half
                    int idx = pos & (OWN_CTA - 1);
                    float4 v;
                    if (h2 == half) {
                        v = *reinterpret_cast<const float4*>(&sh_ex[idx]);
                    } else {
                        uint32_t pa;
                        asm("mapa.shared::cluster.u32 %0, %1, %2;"
                            : "=r"(pa) : "r"(shbase + (uint32_t)idx * 4u), "r"(peer));
                        asm volatile("ld.shared::cluster.v4.f32 {%0,%1,%2,%3}, [%4];"
                                     : "=f"(v.x), "=f"(v.y), "=f"(v.z), "=f"(v.w)
                                     : "r"(pa));
                    }
                    P[2 * g]     = pk(v.x, v.y);
                    P[2 * g + 1] = pk(v.z, v.w);
                }
            }
            __syncthreads();
            asm volatile("barrier.cluster.arrive.aligned;" ::: "memory");
        }

        // ===== one explicit-Euler step, fully in registers =====
        float e[16];
        #pragma unroll
        for (int p = 0; p < 6; p++) upk(P[p], e[2 + 2 * p], e[3 + 2 * p]);
        e[0]  = __shfl_up_sync(0xffffffffu, e[12], 1);
        e[1]  = __shfl_up_sync(0xffffffffu, e[13], 1);
        e[14] = __shfl_down_sync(0xffffffffu, e[2], 1);
        e[15] = __shfl_down_sync(0xffffffffu, e[3], 1);

        u64 A[8];
        A[0] = pk(e[0], e[1]);
        #pragma unroll
        for (int p = 0; p < 6; p++) A[p + 1] = P[p];
        A[7] = pk(e[14], e[15]);
        u64 O[7];
        #pragma unroll
        for (int i = 0; i < 7; i++) O[i] = pk(e[2 * i + 1], e[2 * i + 2]);

        u64 r[6];
        #pragma unroll
        for (int p = 0; p < 6; p++) {
            u64 u   = A[p + 1];
            u64 s1  = add2(O[p + 1], O[p]);
            u64 s2  = add2(A[p + 2], A[p]);
            u64 d1  = fma2(M1, O[p], O[p + 1]);        // up1 - um1
            u64 lin = mul2(C0, u);
            lin = fma2(C1, s1, lin);
            lin = fma2(C2, s2, lin);
            u64 tn  = mul2(AV, u);
            r[p] = fma2(tn, d1, lin);
        }

        // ---- stage owned groups into this frame's ring buffer ----
        {
            float* sb = &sh_st[w][t % NBUF][0];
            #pragma unroll
            for (int g = 0; g < 3; g++) {
                int j = j0 + 4 * g;
                if (j >= GW && j < GW + OWNW) {
                    ulonglong2 v; v.x = r[2 * g]; v.y = r[2 * g + 1];
                    *reinterpret_cast<ulonglong2*>(sb + (j - GW)) = v;
                }
            }
        }
        #pragma unroll
        for (int p = 0; p < 6; p++) P[p] = r[p];

        // ---- every 2 steps: TMA bulk-store frames t and t+1 ----
        if (t & 1) {
            __syncwarp();                       // all lanes' STS for both frames done
            if (lane == 0) {
                asm volatile("fence.proxy.async.shared::cta;" ::: "memory");
                uint32_t sA = st0 + (uint32_t)(((t - 1) % NBUF) * OWNW * 4);
                uint32_t sB = st0 + (uint32_t)((t % NBUF) * OWNW * 4);
                float* gA = gbase + (size_t)(t - 1) * FR;   // frame t
                float* gB = gbase + (size_t)t * FR;         // frame t+1
                asm volatile("cp.async.bulk.global.shared::cta.bulk_group [%0], [%1], %2;"
                             :: "l"(gA), "r"(sA), "r"(1024u) : "memory");
                asm volatile("cp.async.bulk.global.shared::cta.bulk_group [%0], [%1], %2;"
                             :: "l"(gB), "r"(sB), "r"(1024u) : "memory");
                asm volatile("cp.async.bulk.commit_group;" ::: "memory");
                asm volatile("cp.async.bulk.wait_group.read 2;" ::: "memory");
            }
            __syncwarp();                       // buffer-free info published to lanes
        }
    }

    // flush all outstanding bulk stores (lanes without groups pass immediately)
    asm volatile("cp.async.bulk.wait_group 0;" ::: "memory");

    // pair the final outstanding cluster arrive
    asm volatile("barrier.cluster.wait.aligned;" ::: "memory");
}

extern "C" void kernel_launch(void* const* d_in, const int* in_sizes, int n_in,
                              void* d_out, int out_size) {
    const float* u0    = (const float*)d_in[0];
    const float* c     = (const float*)d_in[1];
    const float* alpha = (const float*)d_in[2];
    const float* beta  = (const float*)d_in[3];
    float* out = (float*)d_out;

    ks_kernel<<<BATCH * 2, THREADS>>>(u0, c, alpha, beta, out);
}